// round 14
// baseline (speedup 1.0000x reference)
#include <cuda_runtime.h>
#include <cstdint>

#define B_  16
#define Q_  256
#define K_  256
#define H_  256
#define DV_ 256

__device__ float g_qp[B_ * Q_ * H_];
__device__ float g_kp[B_ * K_ * H_];
__device__ float g_scores[B_ * Q_ * K_];

__device__ __forceinline__ float tanh_fast(float x) {
    float y;
    asm("tanh.approx.f32 %0, %1;" : "=f"(y) : "f"(x));
    return y;
}

// ---------------------------------------------------------------------------
// Kernel 1: projection GEMM, both projections in one launch (R13 exact).
// ---------------------------------------------------------------------------
__global__ __launch_bounds__(256) void proj_gemm2(const float* __restrict__ Aq,
                                                  const float* __restrict__ Wq,
                                                  const float* __restrict__ Ak,
                                                  const float* __restrict__ Wk) {
    constexpr int BM = 64, BN = 64, BK = 32;
    __shared__ float As[BK][BM + 4];
    __shared__ float Bs[BK][BN + 4];

    const float* __restrict__ A;
    const float* __restrict__ W;
    float* __restrict__ C;
    if (blockIdx.z == 0) { A = Aq; W = Wq; C = g_qp; }
    else                 { A = Ak; W = Wk; C = g_kp; }

    const int tid = threadIdx.x;
    const int m0 = blockIdx.y * BM;
    const int n0 = blockIdx.x * BN;
    const int ty = tid >> 4;
    const int tx = tid & 15;

    float acc[4][4];
#pragma unroll
    for (int i = 0; i < 4; i++)
#pragma unroll
        for (int j = 0; j < 4; j++) acc[i][j] = 0.0f;

    const int lr = tid >> 3;
    const int lc = (tid & 7) * 4;

    for (int kt = 0; kt < H_; kt += BK) {
        float4 a0 = *(const float4*)&A[(m0 + lr) * H_ + kt + lc];
        float4 a1 = *(const float4*)&A[(m0 + lr + 32) * H_ + kt + lc];
        float4 b0 = *(const float4*)&W[(n0 + lr) * H_ + kt + lc];
        float4 b1 = *(const float4*)&W[(n0 + lr + 32) * H_ + kt + lc];

        As[lc + 0][lr] = a0.x; As[lc + 1][lr] = a0.y;
        As[lc + 2][lr] = a0.z; As[lc + 3][lr] = a0.w;
        As[lc + 0][lr + 32] = a1.x; As[lc + 1][lr + 32] = a1.y;
        As[lc + 2][lr + 32] = a1.z; As[lc + 3][lr + 32] = a1.w;
        Bs[lc + 0][lr] = b0.x; Bs[lc + 1][lr] = b0.y;
        Bs[lc + 2][lr] = b0.z; Bs[lc + 3][lr] = b0.w;
        Bs[lc + 0][lr + 32] = b1.x; Bs[lc + 1][lr + 32] = b1.y;
        Bs[lc + 2][lr + 32] = b1.z; Bs[lc + 3][lr + 32] = b1.w;

        __syncthreads();

#pragma unroll
        for (int kk = 0; kk < BK; kk++) {
            float a[4], b[4];
#pragma unroll
            for (int i = 0; i < 4; i++) a[i] = As[kk][ty * 4 + i];
#pragma unroll
            for (int j = 0; j < 4; j++) b[j] = Bs[kk][tx * 4 + j];
#pragma unroll
            for (int i = 0; i < 4; i++)
#pragma unroll
                for (int j = 0; j < 4; j++) acc[i][j] += a[i] * b[j];
        }
        __syncthreads();
    }

#pragma unroll
    for (int i = 0; i < 4; i++) {
        float4 v;
        v.x = acc[i][0]; v.y = acc[i][1]; v.z = acc[i][2]; v.w = acc[i][3];
        *(float4*)&C[(m0 + ty * 4 + i) * H_ + n0 + tx * 4] = v;
    }
}

// ---------------------------------------------------------------------------
// Kernel 2: scores — R1 fp32 MUFU version (at the MUFU floor).
// ---------------------------------------------------------------------------
__global__ __launch_bounds__(256) void scores_kernel(const float* __restrict__ wv) {
    const int b = blockIdx.z;
    const int q0 = blockIdx.y * 32;
    const int k0 = blockIdx.x * 32;

    __shared__ float qs[32][33];
    __shared__ float ks[32][33];
    __shared__ float ws[H_];

    const int tid = threadIdx.x;
    ws[tid] = wv[tid];

    const int ty = tid >> 4;
    const int tx = tid & 15;

    const float* qbase = g_qp + (b * Q_ + q0) * H_;
    const float* kbase = g_kp + (b * K_ + k0) * H_;

    float a00 = 0.f, a01 = 0.f, a10 = 0.f, a11 = 0.f;

    const int lr = tid >> 5;
    const int lc = tid & 31;

    for (int hc = 0; hc < H_; hc += 32) {
        __syncthreads();
#pragma unroll
        for (int rr = 0; rr < 4; rr++) {
            int row = lr + rr * 8;
            qs[row][lc] = qbase[row * H_ + hc + lc];
            ks[row][lc] = kbase[row * H_ + hc + lc];
        }
        __syncthreads();

#pragma unroll
        for (int hh = 0; hh < 32; hh++) {
            float w = ws[hc + hh];
            float qv0 = qs[ty * 2 + 0][hh];
            float qv1 = qs[ty * 2 + 1][hh];
            float kv0 = ks[tx * 2 + 0][hh];
            float kv1 = ks[tx * 2 + 1][hh];
            a00 += w * tanh_fast(qv0 + kv0);
            a01 += w * tanh_fast(qv0 + kv1);
            a10 += w * tanh_fast(qv1 + kv0);
            a11 += w * tanh_fast(qv1 + kv1);
        }
    }

    float* sbase = g_scores + (b * Q_ + q0) * K_ + k0;
    *(float2*)&sbase[(ty * 2 + 0) * K_ + tx * 2] = make_float2(a00, a01);
    *(float2*)&sbase[(ty * 2 + 1) * K_ + tx * 2] = make_float2(a10, a11);
}

// ---------------------------------------------------------------------------
// Kernel 3: in-place row softmax over g_scores. One warp per row.
// ---------------------------------------------------------------------------
__global__ __launch_bounds__(256) void softmax_inplace() {
    const int row = blockIdx.x * 8 + (threadIdx.x >> 5);
    const int lane = threadIdx.x & 31;
    float* srow = g_scores + (size_t)row * K_;

    float4 v0 = *(const float4*)&srow[lane * 4];
    float4 v1 = *(const float4*)&srow[128 + lane * 4];

    float mx = fmaxf(fmaxf(fmaxf(v0.x, v0.y), fmaxf(v0.z, v0.w)),
                     fmaxf(fmaxf(v1.x, v1.y), fmaxf(v1.z, v1.w)));
#pragma unroll
    for (int off = 16; off; off >>= 1)
        mx = fmaxf(mx, __shfl_xor_sync(0xffffffffu, mx, off));

    v0.x = __expf(v0.x - mx); v0.y = __expf(v0.y - mx);
    v0.z = __expf(v0.z - mx); v0.w = __expf(v0.w - mx);
    v1.x = __expf(v1.x - mx); v1.y = __expf(v1.y - mx);
    v1.z = __expf(v1.z - mx); v1.w = __expf(v1.w - mx);

    float s = (v0.x + v0.y + v0.z + v0.w) + (v1.x + v1.y + v1.z + v1.w);
#pragma unroll
    for (int off = 16; off; off >>= 1)
        s += __shfl_xor_sync(0xffffffffu, s, off);
    const float inv = 1.0f / s;

    v0.x *= inv; v0.y *= inv; v0.z *= inv; v0.w *= inv;
    v1.x *= inv; v1.y *= inv; v1.z *= inv; v1.w *= inv;

    *(float4*)&srow[lane * 4] = v0;
    *(float4*)&srow[128 + lane * 4] = v1;
}

// ---------------------------------------------------------------------------
// Kernel 4: AV GEMM — BM=32, BN=64, 128 threads, 4x4 thread tile.
// Grid (4, 128) = 512 blocks (was 256) to fix wave imbalance / tail.
// ---------------------------------------------------------------------------
__global__ __launch_bounds__(128) void av_gemm32(const float* __restrict__ V,
                                                 float* __restrict__ out) {
    constexpr int BM = 32, BN = 64, BK = 32;
    __shared__ float As[BK][BM + 4];   // [k][m], 4.6 KB
    __shared__ float Bs[BK][BN + 4];   // [k][n], 8.7 KB

    const int tid = threadIdx.x;
    const int m0 = blockIdx.y * BM;
    const int n0 = blockIdx.x * BN;
    const int b = m0 >> 8;
    const float* __restrict__ P = g_scores;
    const float* __restrict__ Vb = V + (size_t)b * K_ * DV_;

    const int ty = tid >> 4;        // 0..7  -> rows ty*4..+3
    const int tx = tid & 15;        // 0..15 -> cols tx*4..+3

    // loaders
    const int ar = tid >> 2;        // 0..31 (P row)
    const int ac = (tid & 3) * 8;   // 0,8,16,24 (k col, 2x float4)
    const int vr = tid >> 2;        // 0..31 (V k-row)
    const int vc = (tid & 3) * 16;  // 0,16,32,48 (4x float4)

    float acc[4][4];
#pragma unroll
    for (int i = 0; i < 4; i++)
#pragma unroll
        for (int j = 0; j < 4; j++) acc[i][j] = 0.0f;

    for (int kt = 0; kt < K_; kt += BK) {
        float4 a0 = *(const float4*)&P[(size_t)(m0 + ar) * K_ + kt + ac];
        float4 a1 = *(const float4*)&P[(size_t)(m0 + ar) * K_ + kt + ac + 4];
        const float* vrow = &Vb[(size_t)(kt + vr) * DV_ + n0 + vc];
        float4 b0 = *(const float4*)&vrow[0];
        float4 b1 = *(const float4*)&vrow[4];
        float4 b2 = *(const float4*)&vrow[8];
        float4 b3 = *(const float4*)&vrow[12];

        As[ac + 0][ar] = a0.x; As[ac + 1][ar] = a0.y;
        As[ac + 2][ar] = a0.z; As[ac + 3][ar] = a0.w;
        As[ac + 4][ar] = a1.x; As[ac + 5][ar] = a1.y;
        As[ac + 6][ar] = a1.z; As[ac + 7][ar] = a1.w;
        *(float4*)&Bs[vr][vc + 0]  = b0;
        *(float4*)&Bs[vr][vc + 4]  = b1;
        *(float4*)&Bs[vr][vc + 8]  = b2;
        *(float4*)&Bs[vr][vc + 12] = b3;

        __syncthreads();

#pragma unroll
        for (int kk = 0; kk < BK; kk++) {
            float a[4], bb[4];
#pragma unroll
            for (int i = 0; i < 4; i++) a[i] = As[kk][ty * 4 + i];
#pragma unroll
            for (int j = 0; j < 4; j++) bb[j] = Bs[kk][tx * 4 + j];
#pragma unroll
            for (int i = 0; i < 4; i++)
#pragma unroll
                for (int j = 0; j < 4; j++) acc[i][j] += a[i] * bb[j];
        }
        __syncthreads();
    }

#pragma unroll
    for (int i = 0; i < 4; i++) {
        float4 v;
        v.x = acc[i][0]; v.y = acc[i][1]; v.z = acc[i][2]; v.w = acc[i][3];
        *(float4*)&out[(size_t)(m0 + ty * 4 + i) * DV_ + n0 + tx * 4] = v;
    }
}

// ---------------------------------------------------------------------------
extern "C" void kernel_launch(void* const* d_in, const int* in_sizes, int n_in,
                              void* d_out, int out_size) {
    const float* queries = (const float*)d_in[0];
    const float* keys    = (const float*)d_in[1];
    const float* values  = (const float*)d_in[2];
    const float* W_q     = (const float*)d_in[3];
    const float* W_k     = (const float*)d_in[4];
    const float* w_v     = (const float*)d_in[5];
    float* out = (float*)d_out;

    dim3 gproj(H_ / 64, (B_ * Q_) / 64, 2);
    proj_gemm2<<<gproj, 256>>>(queries, W_q, keys, W_k);

    dim3 gscores(K_ / 32, Q_ / 32, B_);
    scores_kernel<<<gscores, 256>>>(w_v);

    softmax_inplace<<<(B_ * Q_) / 8, 256>>>();

    dim3 gav(DV_ / 64, (B_ * Q_) / 32);
    av_gemm32<<<gav, 128>>>(values, out);
}

// round 15
// speedup vs baseline: 1.0207x; 1.0207x over previous
#include <cuda_runtime.h>
#include <cstdint>

#define B_  16
#define Q_  256
#define K_  256
#define H_  256
#define DV_ 256

__device__ float g_qp[B_ * Q_ * H_];
__device__ float g_kp[B_ * K_ * H_];
__device__ float g_scores[B_ * Q_ * K_];

__device__ __forceinline__ float tanh_fast(float x) {
    float y;
    asm("tanh.approx.f32 %0, %1;" : "=f"(y) : "f"(x));
    return y;
}

// ---------------------------------------------------------------------------
// Kernel 1: projection GEMM, both projections in one launch (R13 exact).
// ---------------------------------------------------------------------------
__global__ __launch_bounds__(256) void proj_gemm2(const float* __restrict__ Aq,
                                                  const float* __restrict__ Wq,
                                                  const float* __restrict__ Ak,
                                                  const float* __restrict__ Wk) {
    constexpr int BM = 64, BN = 64, BK = 32;
    __shared__ float As[BK][BM + 4];
    __shared__ float Bs[BK][BN + 4];

    const float* __restrict__ A;
    const float* __restrict__ W;
    float* __restrict__ C;
    if (blockIdx.z == 0) { A = Aq; W = Wq; C = g_qp; }
    else                 { A = Ak; W = Wk; C = g_kp; }

    const int tid = threadIdx.x;
    const int m0 = blockIdx.y * BM;
    const int n0 = blockIdx.x * BN;
    const int ty = tid >> 4;
    const int tx = tid & 15;

    float acc[4][4];
#pragma unroll
    for (int i = 0; i < 4; i++)
#pragma unroll
        for (int j = 0; j < 4; j++) acc[i][j] = 0.0f;

    const int lr = tid >> 3;
    const int lc = (tid & 7) * 4;

    for (int kt = 0; kt < H_; kt += BK) {
        float4 a0 = *(const float4*)&A[(m0 + lr) * H_ + kt + lc];
        float4 a1 = *(const float4*)&A[(m0 + lr + 32) * H_ + kt + lc];
        float4 b0 = *(const float4*)&W[(n0 + lr) * H_ + kt + lc];
        float4 b1 = *(const float4*)&W[(n0 + lr + 32) * H_ + kt + lc];

        As[lc + 0][lr] = a0.x; As[lc + 1][lr] = a0.y;
        As[lc + 2][lr] = a0.z; As[lc + 3][lr] = a0.w;
        As[lc + 0][lr + 32] = a1.x; As[lc + 1][lr + 32] = a1.y;
        As[lc + 2][lr + 32] = a1.z; As[lc + 3][lr + 32] = a1.w;
        Bs[lc + 0][lr] = b0.x; Bs[lc + 1][lr] = b0.y;
        Bs[lc + 2][lr] = b0.z; Bs[lc + 3][lr] = b0.w;
        Bs[lc + 0][lr + 32] = b1.x; Bs[lc + 1][lr + 32] = b1.y;
        Bs[lc + 2][lr + 32] = b1.z; Bs[lc + 3][lr + 32] = b1.w;

        __syncthreads();

#pragma unroll
        for (int kk = 0; kk < BK; kk++) {
            float a[4], b[4];
#pragma unroll
            for (int i = 0; i < 4; i++) a[i] = As[kk][ty * 4 + i];
#pragma unroll
            for (int j = 0; j < 4; j++) b[j] = Bs[kk][tx * 4 + j];
#pragma unroll
            for (int i = 0; i < 4; i++)
#pragma unroll
                for (int j = 0; j < 4; j++) acc[i][j] += a[i] * b[j];
        }
        __syncthreads();
    }

#pragma unroll
    for (int i = 0; i < 4; i++) {
        float4 v;
        v.x = acc[i][0]; v.y = acc[i][1]; v.z = acc[i][2]; v.w = acc[i][3];
        *(float4*)&C[(m0 + ty * 4 + i) * H_ + n0 + tx * 4] = v;
    }
}

// ---------------------------------------------------------------------------
// Kernel 2: scores — R1 fp32 MUFU version (at the MUFU floor).
// ---------------------------------------------------------------------------
__global__ __launch_bounds__(256) void scores_kernel(const float* __restrict__ wv) {
    const int b = blockIdx.z;
    const int q0 = blockIdx.y * 32;
    const int k0 = blockIdx.x * 32;

    __shared__ float qs[32][33];
    __shared__ float ks[32][33];
    __shared__ float ws[H_];

    const int tid = threadIdx.x;
    ws[tid] = wv[tid];

    const int ty = tid >> 4;
    const int tx = tid & 15;

    const float* qbase = g_qp + (b * Q_ + q0) * H_;
    const float* kbase = g_kp + (b * K_ + k0) * H_;

    float a00 = 0.f, a01 = 0.f, a10 = 0.f, a11 = 0.f;

    const int lr = tid >> 5;
    const int lc = tid & 31;

    for (int hc = 0; hc < H_; hc += 32) {
        __syncthreads();
#pragma unroll
        for (int rr = 0; rr < 4; rr++) {
            int row = lr + rr * 8;
            qs[row][lc] = qbase[row * H_ + hc + lc];
            ks[row][lc] = kbase[row * H_ + hc + lc];
        }
        __syncthreads();

#pragma unroll
        for (int hh = 0; hh < 32; hh++) {
            float w = ws[hc + hh];
            float qv0 = qs[ty * 2 + 0][hh];
            float qv1 = qs[ty * 2 + 1][hh];
            float kv0 = ks[tx * 2 + 0][hh];
            float kv1 = ks[tx * 2 + 1][hh];
            a00 += w * tanh_fast(qv0 + kv0);
            a01 += w * tanh_fast(qv0 + kv1);
            a10 += w * tanh_fast(qv1 + kv0);
            a11 += w * tanh_fast(qv1 + kv1);
        }
    }

    float* sbase = g_scores + (b * Q_ + q0) * K_ + k0;
    *(float2*)&sbase[(ty * 2 + 0) * K_ + tx * 2] = make_float2(a00, a01);
    *(float2*)&sbase[(ty * 2 + 1) * K_ + tx * 2] = make_float2(a10, a11);
}

// ---------------------------------------------------------------------------
// Kernel 3: AV GEMM with in-loader softmax (R13 GEMM body, untouched).
// Step 1: per-block row stats (max, 1/sum-exp) for its 64 rows (L2-hot).
// Step 2: R13 av_gemm loop; As-store applies expf(x - mx) * inv.
// exp rides the otherwise-idle MUFU pipe; FFMA structure identical.
// ---------------------------------------------------------------------------
__global__ __launch_bounds__(256) void av_softmax_gemm(const float* __restrict__ V,
                                                       float* __restrict__ out) {
    constexpr int BM = 64, BN = 64, BK = 32;
    __shared__ float As[BK][BM + 4];
    __shared__ float Bs[BK][BN + 4];
    __shared__ float smx[BM];
    __shared__ float sinv[BM];

    const int tid = threadIdx.x;
    const int m0 = blockIdx.y * BM;
    const int n0 = blockIdx.x * BN;
    const int b = m0 >> 8;
    const float* __restrict__ P = g_scores;
    const float* __restrict__ Vb = V + (size_t)b * K_ * DV_;

    const int w = tid >> 5;
    const int lane = tid & 31;

    // ---- row stats: warp w handles rows w*8 .. w*8+7 ----
#pragma unroll
    for (int i = 0; i < 8; i++) {
        const int r = w * 8 + i;
        const float* srow = P + (size_t)(m0 + r) * K_;
        float4 v0 = *(const float4*)&srow[lane * 4];
        float4 v1 = *(const float4*)&srow[128 + lane * 4];
        float mx = fmaxf(fmaxf(fmaxf(v0.x, v0.y), fmaxf(v0.z, v0.w)),
                         fmaxf(fmaxf(v1.x, v1.y), fmaxf(v1.z, v1.w)));
#pragma unroll
        for (int off = 16; off; off >>= 1)
            mx = fmaxf(mx, __shfl_xor_sync(0xffffffffu, mx, off));
        float s = __expf(v0.x - mx) + __expf(v0.y - mx) +
                  __expf(v0.z - mx) + __expf(v0.w - mx) +
                  __expf(v1.x - mx) + __expf(v1.y - mx) +
                  __expf(v1.z - mx) + __expf(v1.w - mx);
#pragma unroll
        for (int off = 16; off; off >>= 1)
            s += __shfl_xor_sync(0xffffffffu, s, off);
        if (lane == 0) {
            smx[r] = mx;
            sinv[r] = 1.0f / s;
        }
    }
    __syncthreads();

    // ---- GEMM (R13 body; As-store normalizes) ----
    const int ty = tid >> 4;
    const int tx = tid & 15;
    const int lr = tid >> 3;
    const int lc = (tid & 7) * 4;

    const float mx0 = smx[lr],      iv0 = sinv[lr];
    const float mx1 = smx[lr + 32], iv1 = sinv[lr + 32];

    float acc[4][4];
#pragma unroll
    for (int i = 0; i < 4; i++)
#pragma unroll
        for (int j = 0; j < 4; j++) acc[i][j] = 0.0f;

    for (int kt = 0; kt < K_; kt += BK) {
        float4 a0 = *(const float4*)&P[(size_t)(m0 + lr) * K_ + kt + lc];
        float4 a1 = *(const float4*)&P[(size_t)(m0 + lr + 32) * K_ + kt + lc];
        float4 b0 = *(const float4*)&Vb[(size_t)(kt + lr) * DV_ + n0 + lc];
        float4 b1 = *(const float4*)&Vb[(size_t)(kt + lr) * DV_ + n0 + 32 + lc];

        As[lc + 0][lr] = __expf(a0.x - mx0) * iv0;
        As[lc + 1][lr] = __expf(a0.y - mx0) * iv0;
        As[lc + 2][lr] = __expf(a0.z - mx0) * iv0;
        As[lc + 3][lr] = __expf(a0.w - mx0) * iv0;
        As[lc + 0][lr + 32] = __expf(a1.x - mx1) * iv1;
        As[lc + 1][lr + 32] = __expf(a1.y - mx1) * iv1;
        As[lc + 2][lr + 32] = __expf(a1.z - mx1) * iv1;
        As[lc + 3][lr + 32] = __expf(a1.w - mx1) * iv1;
        *(float4*)&Bs[lr][lc]      = b0;
        *(float4*)&Bs[lr][lc + 32] = b1;

        __syncthreads();

#pragma unroll
        for (int kk = 0; kk < BK; kk++) {
            float a[4], bb[4];
#pragma unroll
            for (int i = 0; i < 4; i++) a[i] = As[kk][ty * 4 + i];
#pragma unroll
            for (int j = 0; j < 4; j++) bb[j] = Bs[kk][tx * 4 + j];
#pragma unroll
            for (int i = 0; i < 4; i++)
#pragma unroll
                for (int j = 0; j < 4; j++) acc[i][j] += a[i] * bb[j];
        }
        __syncthreads();
    }

#pragma unroll
    for (int i = 0; i < 4; i++) {
        float4 v;
        v.x = acc[i][0]; v.y = acc[i][1]; v.z = acc[i][2]; v.w = acc[i][3];
        *(float4*)&out[(size_t)(m0 + ty * 4 + i) * DV_ + n0 + tx * 4] = v;
    }
}

// ---------------------------------------------------------------------------
extern "C" void kernel_launch(void* const* d_in, const int* in_sizes, int n_in,
                              void* d_out, int out_size) {
    const float* queries = (const float*)d_in[0];
    const float* keys    = (const float*)d_in[1];
    const float* values  = (const float*)d_in[2];
    const float* W_q     = (const float*)d_in[3];
    const float* W_k     = (const float*)d_in[4];
    const float* w_v     = (const float*)d_in[5];
    float* out = (float*)d_out;

    dim3 gproj(H_ / 64, (B_ * Q_) / 64, 2);
    proj_gemm2<<<gproj, 256>>>(queries, W_q, keys, W_k);

    dim3 gscores(K_ / 32, Q_ / 32, B_);
    scores_kernel<<<gscores, 256>>>(w_v);

    dim3 gav(DV_ / 64, (B_ * Q_) / 64);
    av_softmax_gemm<<<gav, 256>>>(values, out);
}

// round 16
// speedup vs baseline: 1.1021x; 1.0797x over previous
#include <cuda_runtime.h>
#include <cstdint>

#define B_  16
#define Q_  256
#define K_  256
#define H_  256
#define DV_ 256

__device__ float g_qp[B_ * Q_ * H_];
__device__ float g_kp[B_ * K_ * H_];
__device__ float g_scores[B_ * Q_ * K_];

__device__ __forceinline__ float tanh_fast(float x) {
    float y;
    asm("tanh.approx.f32 %0, %1;" : "=f"(y) : "f"(x));
    return y;
}

// ---------------------------------------------------------------------------
// Kernel 1: projection GEMM, both projections via blockIdx.z.
// NEW: BM=128 x BN=64, 8x4 thread tile -> 32 FFMA per 3 LDS.128 per kk.
// (4x4 tile was smem-crossbar/FMA co-bound at ~42us; this breaks the tie.)
// ---------------------------------------------------------------------------
__global__ __launch_bounds__(256) void proj_gemm3(const float* __restrict__ Aq,
                                                  const float* __restrict__ Wq,
                                                  const float* __restrict__ Ak,
                                                  const float* __restrict__ Wk) {
    constexpr int BM = 128, BN = 64, BK = 32;
    __shared__ float As[BK][BM + 4];   // [k][m], stride 132
    __shared__ float Bs[BK][BN + 4];   // [k][n], stride 68

    const float* __restrict__ A;
    const float* __restrict__ W;
    float* __restrict__ C;
    if (blockIdx.z == 0) { A = Aq; W = Wq; C = g_qp; }
    else                 { A = Ak; W = Wk; C = g_kp; }

    const int tid = threadIdx.x;
    const int m0 = blockIdx.y * BM;
    const int n0 = blockIdx.x * BN;
    const int ty = tid >> 4;        // 0..15 -> rows ty*8..+7
    const int tx = tid & 15;        // 0..15 -> cols tx*4..+3
    const int lr = tid >> 3;        // 0..31
    const int lc = (tid & 7) * 4;   // 0..28

    float acc[8][4];
#pragma unroll
    for (int i = 0; i < 8; i++)
#pragma unroll
        for (int j = 0; j < 4; j++) acc[i][j] = 0.0f;

    for (int kt = 0; kt < H_; kt += BK) {
        // A tile: 128 rows x 32 cols, 4 row-groups, transposed store
#pragma unroll
        for (int g = 0; g < 4; g++) {
            float4 a = *(const float4*)&A[(size_t)(m0 + lr + 32 * g) * H_ + kt + lc];
            As[lc + 0][lr + 32 * g] = a.x;
            As[lc + 1][lr + 32 * g] = a.y;
            As[lc + 2][lr + 32 * g] = a.z;
            As[lc + 3][lr + 32 * g] = a.w;
        }
        // B tile: 64 rows x 32 cols, 2 row-groups, transposed store
#pragma unroll
        for (int g = 0; g < 2; g++) {
            float4 b = *(const float4*)&W[(size_t)(n0 + lr + 32 * g) * H_ + kt + lc];
            Bs[lc + 0][lr + 32 * g] = b.x;
            Bs[lc + 1][lr + 32 * g] = b.y;
            Bs[lc + 2][lr + 32 * g] = b.z;
            Bs[lc + 3][lr + 32 * g] = b.w;
        }
        __syncthreads();

#pragma unroll
        for (int kk = 0; kk < BK; kk++) {
            float a[8], b[4];
            *(float4*)&a[0] = *(const float4*)&As[kk][ty * 8];
            *(float4*)&a[4] = *(const float4*)&As[kk][ty * 8 + 4];
            *(float4*)&b[0] = *(const float4*)&Bs[kk][tx * 4];
#pragma unroll
            for (int i = 0; i < 8; i++)
#pragma unroll
                for (int j = 0; j < 4; j++) acc[i][j] += a[i] * b[j];
        }
        __syncthreads();
    }

#pragma unroll
    for (int i = 0; i < 8; i++) {
        float4 v;
        v.x = acc[i][0]; v.y = acc[i][1]; v.z = acc[i][2]; v.w = acc[i][3];
        *(float4*)&C[(size_t)(m0 + ty * 8 + i) * H_ + n0 + tx * 4] = v;
    }
}

// ---------------------------------------------------------------------------
// Kernel 2: scores — R1 fp32 MUFU version (at the MUFU floor).
// ---------------------------------------------------------------------------
__global__ __launch_bounds__(256) void scores_kernel(const float* __restrict__ wv) {
    const int b = blockIdx.z;
    const int q0 = blockIdx.y * 32;
    const int k0 = blockIdx.x * 32;

    __shared__ float qs[32][33];
    __shared__ float ks[32][33];
    __shared__ float ws[H_];

    const int tid = threadIdx.x;
    ws[tid] = wv[tid];

    const int ty = tid >> 4;
    const int tx = tid & 15;

    const float* qbase = g_qp + (b * Q_ + q0) * H_;
    const float* kbase = g_kp + (b * K_ + k0) * H_;

    float a00 = 0.f, a01 = 0.f, a10 = 0.f, a11 = 0.f;

    const int lr = tid >> 5;
    const int lc = tid & 31;

    for (int hc = 0; hc < H_; hc += 32) {
        __syncthreads();
#pragma unroll
        for (int rr = 0; rr < 4; rr++) {
            int row = lr + rr * 8;
            qs[row][lc] = qbase[row * H_ + hc + lc];
            ks[row][lc] = kbase[row * H_ + hc + lc];
        }
        __syncthreads();

#pragma unroll
        for (int hh = 0; hh < 32; hh++) {
            float w = ws[hc + hh];
            float qv0 = qs[ty * 2 + 0][hh];
            float qv1 = qs[ty * 2 + 1][hh];
            float kv0 = ks[tx * 2 + 0][hh];
            float kv1 = ks[tx * 2 + 1][hh];
            a00 += w * tanh_fast(qv0 + kv0);
            a01 += w * tanh_fast(qv0 + kv1);
            a10 += w * tanh_fast(qv1 + kv0);
            a11 += w * tanh_fast(qv1 + kv1);
        }
    }

    float* sbase = g_scores + (b * Q_ + q0) * K_ + k0;
    *(float2*)&sbase[(ty * 2 + 0) * K_ + tx * 2] = make_float2(a00, a01);
    *(float2*)&sbase[(ty * 2 + 1) * K_ + tx * 2] = make_float2(a10, a11);
}

// ---------------------------------------------------------------------------
// Kernel 3: in-place row softmax over g_scores. One warp per row.
// ---------------------------------------------------------------------------
__global__ __launch_bounds__(256) void softmax_inplace() {
    const int row = blockIdx.x * 8 + (threadIdx.x >> 5);
    const int lane = threadIdx.x & 31;
    float* srow = g_scores + (size_t)row * K_;

    float4 v0 = *(const float4*)&srow[lane * 4];
    float4 v1 = *(const float4*)&srow[128 + lane * 4];

    float mx = fmaxf(fmaxf(fmaxf(v0.x, v0.y), fmaxf(v0.z, v0.w)),
                     fmaxf(fmaxf(v1.x, v1.y), fmaxf(v1.z, v1.w)));
#pragma unroll
    for (int off = 16; off; off >>= 1)
        mx = fmaxf(mx, __shfl_xor_sync(0xffffffffu, mx, off));

    v0.x = __expf(v0.x - mx); v0.y = __expf(v0.y - mx);
    v0.z = __expf(v0.z - mx); v0.w = __expf(v0.w - mx);
    v1.x = __expf(v1.x - mx); v1.y = __expf(v1.y - mx);
    v1.z = __expf(v1.z - mx); v1.w = __expf(v1.w - mx);

    float s = (v0.x + v0.y + v0.z + v0.w) + (v1.x + v1.y + v1.z + v1.w);
#pragma unroll
    for (int off = 16; off; off >>= 1)
        s += __shfl_xor_sync(0xffffffffu, s, off);
    const float inv = 1.0f / s;

    v0.x *= inv; v0.y *= inv; v0.z *= inv; v0.w *= inv;
    v1.x *= inv; v1.y *= inv; v1.z *= inv; v1.w *= inv;

    *(float4*)&srow[lane * 4] = v0;
    *(float4*)&srow[128 + lane * 4] = v1;
}

// ---------------------------------------------------------------------------
// Kernel 4: AV GEMM (R7/R13 exact).
// ---------------------------------------------------------------------------
__global__ __launch_bounds__(256) void av_gemm(const float* __restrict__ V,
                                               float* __restrict__ out) {
    constexpr int BM = 64, BN = 64, BK = 32;
    __shared__ float As[BK][BM + 4];
    __shared__ float Bs[BK][BN + 4];

    const int tid = threadIdx.x;
    const int m0 = blockIdx.y * BM;
    const int n0 = blockIdx.x * BN;
    const int b = m0 >> 8;
    const float* __restrict__ P = g_scores;
    const float* __restrict__ Vb = V + (size_t)b * K_ * DV_;

    const int ty = tid >> 4;
    const int tx = tid & 15;
    const int lr = tid >> 3;
    const int lc = (tid & 7) * 4;

    float acc[4][4];
#pragma unroll
    for (int i = 0; i < 4; i++)
#pragma unroll
        for (int j = 0; j < 4; j++) acc[i][j] = 0.0f;

    for (int kt = 0; kt < K_; kt += BK) {
        float4 a0 = *(const float4*)&P[(size_t)(m0 + lr) * K_ + kt + lc];
        float4 a1 = *(const float4*)&P[(size_t)(m0 + lr + 32) * K_ + kt + lc];
        float4 b0 = *(const float4*)&Vb[(size_t)(kt + lr) * DV_ + n0 + lc];
        float4 b1 = *(const float4*)&Vb[(size_t)(kt + lr) * DV_ + n0 + 32 + lc];

        As[lc + 0][lr] = a0.x; As[lc + 1][lr] = a0.y;
        As[lc + 2][lr] = a0.z; As[lc + 3][lr] = a0.w;
        As[lc + 0][lr + 32] = a1.x; As[lc + 1][lr + 32] = a1.y;
        As[lc + 2][lr + 32] = a1.z; As[lc + 3][lr + 32] = a1.w;
        *(float4*)&Bs[lr][lc]      = b0;
        *(float4*)&Bs[lr][lc + 32] = b1;

        __syncthreads();

#pragma unroll
        for (int kk = 0; kk < BK; kk++) {
            float a[4], bb[4];
#pragma unroll
            for (int i = 0; i < 4; i++) a[i] = As[kk][ty * 4 + i];
#pragma unroll
            for (int j = 0; j < 4; j++) bb[j] = Bs[kk][tx * 4 + j];
#pragma unroll
            for (int i = 0; i < 4; i++)
#pragma unroll
                for (int j = 0; j < 4; j++) acc[i][j] += a[i] * bb[j];
        }
        __syncthreads();
    }

#pragma unroll
    for (int i = 0; i < 4; i++) {
        float4 v;
        v.x = acc[i][0]; v.y = acc[i][1]; v.z = acc[i][2]; v.w = acc[i][3];
        *(float4*)&out[(size_t)(m0 + ty * 4 + i) * DV_ + n0 + tx * 4] = v;
    }
}

// ---------------------------------------------------------------------------
extern "C" void kernel_launch(void* const* d_in, const int* in_sizes, int n_in,
                              void* d_out, int out_size) {
    const float* queries = (const float*)d_in[0];
    const float* keys    = (const float*)d_in[1];
    const float* values  = (const float*)d_in[2];
    const float* W_q     = (const float*)d_in[3];
    const float* W_k     = (const float*)d_in[4];
    const float* w_v     = (const float*)d_in[5];
    float* out = (float*)d_out;

    dim3 gproj(H_ / 64, (B_ * Q_) / 128, 2);
    proj_gemm3<<<gproj, 256>>>(queries, W_q, keys, W_k);

    dim3 gscores(K_ / 32, Q_ / 32, B_);
    scores_kernel<<<gscores, 256>>>(w_v);

    softmax_inplace<<<(B_ * Q_) / 8, 256>>>();

    dim3 gav(DV_ / 64, (B_ * Q_) / 64);
    av_gemm<<<gav, 256>>>(values, out);
}